// round 6
// baseline (speedup 1.0000x reference)
#include <cuda_runtime.h>

typedef unsigned long long ull;

#define BB 64
#define NN 16
#define TT 128
#define HH 256
#define NP1 17
#define NPAIRS (BB*NP1)   // 1088

// ---------------- scratch (static device globals; no runtime allocation) ----------------
__device__ float g_q  [BB*TT*HH];     // node @ Wq^T
__device__ float g_t2 [BB*TT*HH];     // q @ Wb
__device__ float g_P  [BB*TT*HH];     // (q @ Wb) @ Wk
__device__ float g_Afb[(size_t)NPAIRS*TT*TT]; // fallback A buffer if A is not part of d_out

// ---------------- f32x2 helpers (Blackwell packed fp32, 2x FFMA throughput) -------------
__device__ __forceinline__ void fma2(ull& d, ull a, ull b){
    asm("fma.rn.f32x2 %0, %1, %2, %0;" : "+l"(d) : "l"(a), "l"(b));
}
__device__ __forceinline__ ull pk2(float x, float y){
    ull r; asm("mov.b64 %0, {%1, %2};" : "=l"(r) : "f"(x), "f"(y)); return r;
}
__device__ __forceinline__ float2 upk(ull v){
    float2 f; asm("mov.b64 {%0, %1}, %2;" : "=f"(f.x), "=f"(f.y) : "l"(v)); return f;
}

// ---------------- smem staging ----------------
// dst[k][i] = src[i*ld + k]   (transpose-stage: source is i-major, we need k-major)
// 256 threads x 2 x float4 = 2048 floats = full 16x128 tile
__device__ __forceinline__ void stage_T(float (*dst)[128], const float* __restrict__ src,
                                        int ld, int tid){
    int c4 = (tid & 3) * 4;   // k offset (float4 group)
    int r  = tid >> 2;        // 0..63
    #pragma unroll
    for (int h2 = 0; h2 < 2; ++h2){
        int row = r + h2*64;
        float4 v = *(const float4*)(src + (size_t)row*ld + c4);
        dst[c4+0][row] = v.x; dst[c4+1][row] = v.y;
        dst[c4+2][row] = v.z; dst[c4+3][row] = v.w;
    }
}
// dst[k][n] = src[k*ld + n]   (direct-stage: source already k-major)
// FIXED: each thread now writes TWO float4s (cols n4 and n4+64) -> full 16x128 tile.
// Previous version covered only columns 0..63, leaving half of Bs stale.
__device__ __forceinline__ void stage_D(float (*dst)[128], const float* __restrict__ src,
                                        int ld, int tid){
    int n4 = (tid & 15) * 4;
    int k  = tid >> 4;        // 0..15
    *(float4*)(&dst[k][n4])      = *(const float4*)(src + (size_t)k*ld + n4);
    *(float4*)(&dst[k][n4 + 64]) = *(const float4*)(src + (size_t)k*ld + n4 + 64);
}

// ---------------- 128x128 tile micro-kernel, one BK=16 slab ----------------
// acc[i][jp]: rows i (0..3 -> ty*4+i ; 4..7 -> 64+ty*4+i-4), col pairs jp over
// {tx*4+0/1, tx*4+2/3, 64+tx*4+0/1, 64+tx*4+2/3}
__device__ __forceinline__ void mm16(ull acc[8][4], float (*As)[128], float (*Bs)[128],
                                     int tx, int ty){
    #pragma unroll
    for (int k = 0; k < 16; ++k){
        float4 a0 = *(const float4*)(&As[k][ty*4]);
        float4 a1 = *(const float4*)(&As[k][64+ty*4]);
        float4 b0 = *(const float4*)(&Bs[k][tx*4]);
        float4 b1 = *(const float4*)(&Bs[k][64+tx*4]);
        ull bb0 = pk2(b0.x,b0.y), bb1 = pk2(b0.z,b0.w);
        ull bb2 = pk2(b1.x,b1.y), bb3 = pk2(b1.z,b1.w);
        float av[8] = {a0.x,a0.y,a0.z,a0.w,a1.x,a1.y,a1.z,a1.w};
        #pragma unroll
        for (int i = 0; i < 8; ++i){
            ull ad = pk2(av[i], av[i]);
            fma2(acc[i][0], ad, bb0);
            fma2(acc[i][1], ad, bb1);
            fma2(acc[i][2], ad, bb2);
            fma2(acc[i][3], ad, bb3);
        }
    }
}

__device__ __forceinline__ int row_of(int i, int ty){
    return (i < 4) ? (ty*4 + i) : (64 + ty*4 + (i-4));
}

__device__ __forceinline__ const float* pair_base(int p, const float* node, const float* neigh){
    int b = p / NP1, n = p % NP1;
    return (n == 0) ? node  + (size_t)b*TT*HH
                    : neigh + (size_t)(b*NN + (n-1))*TT*HH;
}

// ================= K1..K3: flat [8192,256] x [256,256] GEMM chain ========================
// STEP 0: g_q = node @ Wq^T ; STEP 1: g_t2 = g_q @ Wb ; STEP 2: g_P = g_t2 @ Wk
template<int STEP>
__global__ void __launch_bounds__(256, 2) sgemm_flat(const float* __restrict__ Ain,
                                                     const float* __restrict__ W){
    __shared__ float As[16][128], Bs[16][128];
    int tid = threadIdx.x, tx = tid & 15, ty = tid >> 4;
    const float* A = (STEP == 0) ? Ain : (STEP == 1 ? g_q : g_t2);
    float*       C = (STEP == 0) ? g_q : (STEP == 1 ? g_t2 : g_P);
    const float* Ab = A + (size_t)blockIdx.x * 128 * HH;
    int n0 = blockIdx.y * 128;

    ull acc[8][4];
    #pragma unroll
    for (int i=0;i<8;i++){ acc[i][0]=acc[i][1]=acc[i][2]=acc[i][3]=0ULL; }

    for (int kt = 0; kt < HH; kt += 16){
        stage_T(As, Ab + kt, HH, tid);
        if (STEP == 0) stage_T(Bs, W + (size_t)n0*HH + kt, HH, tid);   // B = W^T (W is NK)
        else           stage_D(Bs, W + (size_t)kt*HH + n0, HH, tid);   // B = W   (W is KN)
        __syncthreads();
        mm16(acc, As, Bs, tx, ty);
        __syncthreads();
    }
    float* Cb = C + (size_t)blockIdx.x*128*HH + n0;
    #pragma unroll
    for (int i=0;i<8;i++){
        int row = row_of(i, ty);
        float2 p0=upk(acc[i][0]), p1=upk(acc[i][1]), p2=upk(acc[i][2]), p3=upk(acc[i][3]);
        *(float4*)(Cb + (size_t)row*HH + tx*4)      = make_float4(p0.x,p0.y,p1.x,p1.y);
        *(float4*)(Cb + (size_t)row*HH + 64 + tx*4) = make_float4(p2.x,p2.y,p3.x,p3.y);
    }
}

// ================= K4: S = P_b @ X_p^T  (+bias) -> softmax -> A ==========================
__global__ void __launch_bounds__(256, 2) kernel_S(const float* __restrict__ node,
                                                   const float* __restrict__ neigh,
                                                   const float* __restrict__ bias,
                                                   float* Aout){
    __shared__ float As[16][128], Bs[16][128];
    int tid = threadIdx.x, tx = tid & 15, ty = tid >> 4;
    int p = blockIdx.x, b = p / NP1;
    const float* Pb = g_P + (size_t)b*TT*HH;
    const float* X  = pair_base(p, node, neigh);
    float* Ao = (Aout != nullptr) ? Aout : g_Afb;

    ull acc[8][4];
    #pragma unroll
    for (int i=0;i<8;i++){ acc[i][0]=acc[i][1]=acc[i][2]=acc[i][3]=0ULL; }

    for (int kt = 0; kt < HH; kt += 16){
        stage_T(As, Pb + kt, HH, tid);   // As[k][t] = P[t, kt+k]
        stage_T(Bs, X  + kt, HH, tid);   // Bs[k][s] = X[s, kt+k]
        __syncthreads();
        mm16(acc, As, Bs, tx, ty);
        __syncthreads();
    }

    // unpack S, add bias (broadcast over s), softmax over s (cols of the tile)
    float v[8][8];
    #pragma unroll
    for (int i=0;i<8;i++){
        float2 p0=upk(acc[i][0]), p1=upk(acc[i][1]), p2=upk(acc[i][2]), p3=upk(acc[i][3]);
        v[i][0]=p0.x; v[i][1]=p0.y; v[i][2]=p1.x; v[i][3]=p1.y;
        v[i][4]=p2.x; v[i][5]=p2.y; v[i][6]=p3.x; v[i][7]=p3.y;
    }
    float4 bb0 = *(const float4*)(bias + tx*4);
    float4 bb1 = *(const float4*)(bias + 64 + tx*4);
    float bv[8] = {bb0.x,bb0.y,bb0.z,bb0.w, bb1.x,bb1.y,bb1.z,bb1.w};

    float* Ap = Ao + (size_t)p*TT*TT;
    #pragma unroll
    for (int i=0;i<8;i++){
        #pragma unroll
        for (int j=0;j<8;j++) v[i][j] += bv[j];
        float m = v[i][0];
        #pragma unroll
        for (int j=1;j<8;j++) m = fmaxf(m, v[i][j]);
        #pragma unroll
        for (int o=8;o>=1;o>>=1) m = fmaxf(m, __shfl_xor_sync(0xffffffffu, m, o));
        float s = 0.f;
        #pragma unroll
        for (int j=0;j<8;j++){ v[i][j] = expf(v[i][j] - m); s += v[i][j]; }
        #pragma unroll
        for (int o=8;o>=1;o>>=1) s += __shfl_xor_sync(0xffffffffu, s, o);
        float r = 1.f / s;
        int row = row_of(i, ty);
        *(float4*)(Ap + (size_t)row*TT + tx*4) =
            make_float4(v[i][0]*r, v[i][1]*r, v[i][2]*r, v[i][3]*r);
        *(float4*)(Ap + (size_t)row*TT + 64 + tx*4) =
            make_float4(v[i][4]*r, v[i][5]*r, v[i][6]*r, v[i][7]*r);
    }
}

// ================= K5: fused V = X_p @ Wv^T (tile in smem), then O = A @ V ===============
__global__ void __launch_bounds__(256, 2) kernel_VO(const float* __restrict__ node,
                                                    const float* __restrict__ neigh,
                                                    const float* __restrict__ Wv,
                                                    const float* Ain,
                                                    float* __restrict__ Out){
    extern __shared__ float sm[];
    float (*Vs)[128] = (float (*)[128])sm;                       // 128x128 = 64KB
    float (*As)[128] = (float (*)[128])(sm + 128*128);           // 16x128
    float (*Bs)[128] = (float (*)[128])(sm + 128*128 + 16*128);  // 16x128

    int tid = threadIdx.x, tx = tid & 15, ty = tid >> 4;
    int p = blockIdx.x;
    int n0 = blockIdx.y * 128;       // H column chunk
    const float* X  = pair_base(p, node, neigh);
    const float* Ap = ((Ain != nullptr) ? Ain : (const float*)g_Afb) + (size_t)p*TT*TT;

    ull acc[8][4];
    #pragma unroll
    for (int i=0;i<8;i++){ acc[i][0]=acc[i][1]=acc[i][2]=acc[i][3]=0ULL; }

    // ---- GEMM1: Vtile[s, c] = sum_k X[s,k] * Wv[n0+c, k] ----
    for (int kt = 0; kt < HH; kt += 16){
        stage_T(As, X + kt, HH, tid);                       // As[k][s]
        stage_T(Bs, Wv + (size_t)n0*HH + kt, HH, tid);      // Bs[k][c] = Wv[n0+c, kt+k]
        __syncthreads();
        mm16(acc, As, Bs, tx, ty);
        __syncthreads();
    }
    #pragma unroll
    for (int i=0;i<8;i++){
        int row = row_of(i, ty);
        float2 p0=upk(acc[i][0]), p1=upk(acc[i][1]), p2=upk(acc[i][2]), p3=upk(acc[i][3]);
        *(float4*)(&Vs[row][tx*4])      = make_float4(p0.x,p0.y,p1.x,p1.y);
        *(float4*)(&Vs[row][64+tx*4])   = make_float4(p2.x,p2.y,p3.x,p3.y);
        acc[i][0]=acc[i][1]=acc[i][2]=acc[i][3]=0ULL;
    }
    __syncthreads();

    // ---- GEMM2: O[t, c] = sum_s A[t,s] * Vs[s][c]  (K = 128) ----
    for (int kt = 0; kt < TT; kt += 16){
        stage_T(As, Ap + kt, TT, tid);                      // As[k][t] = A[t, kt+k]
        __syncthreads();
        mm16(acc, As, Vs + kt, tx, ty);                     // Bs := Vs rows kt..kt+15
        __syncthreads();
    }
    float* Ob = Out + (size_t)p*TT*HH + n0;
    #pragma unroll
    for (int i=0;i<8;i++){
        int row = row_of(i, ty);
        float2 p0=upk(acc[i][0]), p1=upk(acc[i][1]), p2=upk(acc[i][2]), p3=upk(acc[i][3]);
        *(float4*)(Ob + (size_t)row*HH + tx*4)      = make_float4(p0.x,p0.y,p1.x,p1.y);
        *(float4*)(Ob + (size_t)row*HH + 64 + tx*4) = make_float4(p2.x,p2.y,p3.x,p3.y);
    }
}

// =========================================================================================
extern "C" void kernel_launch(void* const* d_in, const int* in_sizes, int n_in,
                              void* d_out, int out_size){
    const float* node  = (const float*)d_in[0];
    const float* neigh = (const float*)d_in[1];
    // metadata order: node, neigh, neighbors_number(scalar), Wq, Wk, Wv, Wb, b
    // tolerate a harness that drops the scalar input
    int w = (n_in >= 8) ? 2 : 1;
    const float* Wq = (const float*)d_in[w+1];
    const float* Wk = (const float*)d_in[w+2];
    const float* Wv = (const float*)d_in[w+3];
    const float* Wb = (const float*)d_in[w+4];
    const float* bv = (const float*)d_in[w+5];

    float* out = (float*)d_out;
    const long long O_ELEMS = (long long)NPAIRS*TT*HH;   // 35,651,584
    const long long A_ELEMS = (long long)NPAIRS*TT*TT;   // 17,825,792
    // outputs first, then A (reference returns (outputs, A)); if the harness only
    // checks outputs, keep A in the device fallback buffer.
    float* Aout = ((long long)out_size >= O_ELEMS + A_ELEMS) ? (out + O_ELEMS) : nullptr;

    const int VO_SMEM = (128*128 + 2*16*128) * (int)sizeof(float);  // 81920 B
    cudaFuncSetAttribute(kernel_VO, cudaFuncAttributeMaxDynamicSharedMemorySize, VO_SMEM);

    dim3 thr(256);
    sgemm_flat<0><<<dim3(64,2), thr>>>(node, Wq);        // g_q  = node @ Wq^T
    sgemm_flat<1><<<dim3(64,2), thr>>>(nullptr, Wb);     // g_t2 = g_q @ Wb
    sgemm_flat<2><<<dim3(64,2), thr>>>(nullptr, Wk);     // g_P  = g_t2 @ Wk
    kernel_S <<<dim3(NPAIRS,1), thr>>>(node, neigh, bv, Aout);
    kernel_VO<<<dim3(NPAIRS,2), thr, VO_SMEM>>>(node, neigh, Wv, Aout, out);
}

// round 7
// speedup vs baseline: 1.0040x; 1.0040x over previous
#include <cuda_runtime.h>

typedef unsigned long long ull;

#define BB 64
#define NN 16
#define TT 128
#define HH 256
#define NP1 17
#define NPAIRS (BB*NP1)   // 1088

// ---------------- scratch (static device globals; no runtime allocation) ----------------
__device__ float g_q  [BB*TT*HH];     // node @ Wq^T
__device__ float g_t2 [BB*TT*HH];     // q @ Wb
__device__ float g_P  [BB*TT*HH];     // (q @ Wb) @ Wk
__device__ float g_Afb[(size_t)NPAIRS*TT*TT]; // fallback A buffer if A is not part of d_out

// ---------------- f32x2 helpers (Blackwell packed fp32, 2x FFMA throughput) -------------
__device__ __forceinline__ void fma2(ull& d, ull a, ull b){
    asm("fma.rn.f32x2 %0, %1, %2, %0;" : "+l"(d) : "l"(a), "l"(b));
}
__device__ __forceinline__ ull pk2(float x, float y){
    ull r; asm("mov.b64 %0, {%1, %2};" : "=l"(r) : "f"(x), "f"(y)); return r;
}
__device__ __forceinline__ float2 upk(ull v){
    float2 f; asm("mov.b64 {%0, %1}, %2;" : "=f"(f.x), "=f"(f.y) : "l"(v)); return f;
}

// ---------------- smem staging ----------------
// dst[k][i] = src[i*ld + k]   (transpose-stage: source is i-major, we need k-major)
// 256 threads x 2 x float4 = 2048 floats = full 16x128 tile
__device__ __forceinline__ void stage_T(float (*dst)[128], const float* __restrict__ src,
                                        int ld, int tid){
    int c4 = (tid & 3) * 4;   // k offset (float4 group)
    int r  = tid >> 2;        // 0..63
    #pragma unroll
    for (int h2 = 0; h2 < 2; ++h2){
        int row = r + h2*64;
        float4 v = *(const float4*)(src + (size_t)row*ld + c4);
        dst[c4+0][row] = v.x; dst[c4+1][row] = v.y;
        dst[c4+2][row] = v.z; dst[c4+3][row] = v.w;
    }
}
// dst[k][n] = src[k*ld + n]   (direct-stage: source already k-major)
// FIXED: each thread now writes TWO float4s (cols n4 and n4+64) -> full 16x128 tile.
// Previous version covered only columns 0..63, leaving half of Bs stale.
__device__ __forceinline__ void stage_D(float (*dst)[128], const float* __restrict__ src,
                                        int ld, int tid){
    int n4 = (tid & 15) * 4;
    int k  = tid >> 4;        // 0..15
    *(float4*)(&dst[k][n4])      = *(const float4*)(src + (size_t)k*ld + n4);
    *(float4*)(&dst[k][n4 + 64]) = *(const float4*)(src + (size_t)k*ld + n4 + 64);
}

// ---------------- 128x128 tile micro-kernel, one BK=16 slab ----------------
// acc[i][jp]: rows i (0..3 -> ty*4+i ; 4..7 -> 64+ty*4+i-4), col pairs jp over
// {tx*4+0/1, tx*4+2/3, 64+tx*4+0/1, 64+tx*4+2/3}
__device__ __forceinline__ void mm16(ull acc[8][4], float (*As)[128], float (*Bs)[128],
                                     int tx, int ty){
    #pragma unroll
    for (int k = 0; k < 16; ++k){
        float4 a0 = *(const float4*)(&As[k][ty*4]);
        float4 a1 = *(const float4*)(&As[k][64+ty*4]);
        float4 b0 = *(const float4*)(&Bs[k][tx*4]);
        float4 b1 = *(const float4*)(&Bs[k][64+tx*4]);
        ull bb0 = pk2(b0.x,b0.y), bb1 = pk2(b0.z,b0.w);
        ull bb2 = pk2(b1.x,b1.y), bb3 = pk2(b1.z,b1.w);
        float av[8] = {a0.x,a0.y,a0.z,a0.w,a1.x,a1.y,a1.z,a1.w};
        #pragma unroll
        for (int i = 0; i < 8; ++i){
            ull ad = pk2(av[i], av[i]);
            fma2(acc[i][0], ad, bb0);
            fma2(acc[i][1], ad, bb1);
            fma2(acc[i][2], ad, bb2);
            fma2(acc[i][3], ad, bb3);
        }
    }
}

__device__ __forceinline__ int row_of(int i, int ty){
    return (i < 4) ? (ty*4 + i) : (64 + ty*4 + (i-4));
}

__device__ __forceinline__ const float* pair_base(int p, const float* node, const float* neigh){
    int b = p / NP1, n = p % NP1;
    return (n == 0) ? node  + (size_t)b*TT*HH
                    : neigh + (size_t)(b*NN + (n-1))*TT*HH;
}

// ================= K1..K3: flat [8192,256] x [256,256] GEMM chain ========================
// STEP 0: g_q = node @ Wq^T ; STEP 1: g_t2 = g_q @ Wb ; STEP 2: g_P = g_t2 @ Wk
template<int STEP>
__global__ void __launch_bounds__(256, 2) sgemm_flat(const float* __restrict__ Ain,
                                                     const float* __restrict__ W){
    __shared__ float As[16][128], Bs[16][128];
    int tid = threadIdx.x, tx = tid & 15, ty = tid >> 4;
    const float* A = (STEP == 0) ? Ain : (STEP == 1 ? g_q : g_t2);
    float*       C = (STEP == 0) ? g_q : (STEP == 1 ? g_t2 : g_P);
    const float* Ab = A + (size_t)blockIdx.x * 128 * HH;
    int n0 = blockIdx.y * 128;

    ull acc[8][4];
    #pragma unroll
    for (int i=0;i<8;i++){ acc[i][0]=acc[i][1]=acc[i][2]=acc[i][3]=0ULL; }

    for (int kt = 0; kt < HH; kt += 16){
        stage_T(As, Ab + kt, HH, tid);
        if (STEP == 0) stage_T(Bs, W + (size_t)n0*HH + kt, HH, tid);   // B = W^T (W is NK)
        else           stage_D(Bs, W + (size_t)kt*HH + n0, HH, tid);   // B = W   (W is KN)
        __syncthreads();
        mm16(acc, As, Bs, tx, ty);
        __syncthreads();
    }
    float* Cb = C + (size_t)blockIdx.x*128*HH + n0;
    #pragma unroll
    for (int i=0;i<8;i++){
        int row = row_of(i, ty);
        float2 p0=upk(acc[i][0]), p1=upk(acc[i][1]), p2=upk(acc[i][2]), p3=upk(acc[i][3]);
        *(float4*)(Cb + (size_t)row*HH + tx*4)      = make_float4(p0.x,p0.y,p1.x,p1.y);
        *(float4*)(Cb + (size_t)row*HH + 64 + tx*4) = make_float4(p2.x,p2.y,p3.x,p3.y);
    }
}

// ================= K4: S = P_b @ X_p^T  (+bias) -> softmax -> A ==========================
__global__ void __launch_bounds__(256, 2) kernel_S(const float* __restrict__ node,
                                                   const float* __restrict__ neigh,
                                                   const float* __restrict__ bias,
                                                   float* Aout){
    __shared__ float As[16][128], Bs[16][128];
    int tid = threadIdx.x, tx = tid & 15, ty = tid >> 4;
    int p = blockIdx.x, b = p / NP1;
    const float* Pb = g_P + (size_t)b*TT*HH;
    const float* X  = pair_base(p, node, neigh);
    float* Ao = (Aout != nullptr) ? Aout : g_Afb;

    ull acc[8][4];
    #pragma unroll
    for (int i=0;i<8;i++){ acc[i][0]=acc[i][1]=acc[i][2]=acc[i][3]=0ULL; }

    for (int kt = 0; kt < HH; kt += 16){
        stage_T(As, Pb + kt, HH, tid);   // As[k][t] = P[t, kt+k]
        stage_T(Bs, X  + kt, HH, tid);   // Bs[k][s] = X[s, kt+k]
        __syncthreads();
        mm16(acc, As, Bs, tx, ty);
        __syncthreads();
    }

    // unpack S, add bias (broadcast over s), softmax over s (cols of the tile)
    float v[8][8];
    #pragma unroll
    for (int i=0;i<8;i++){
        float2 p0=upk(acc[i][0]), p1=upk(acc[i][1]), p2=upk(acc[i][2]), p3=upk(acc[i][3]);
        v[i][0]=p0.x; v[i][1]=p0.y; v[i][2]=p1.x; v[i][3]=p1.y;
        v[i][4]=p2.x; v[i][5]=p2.y; v[i][6]=p3.x; v[i][7]=p3.y;
    }
    float4 bb0 = *(const float4*)(bias + tx*4);
    float4 bb1 = *(const float4*)(bias + 64 + tx*4);
    float bv[8] = {bb0.x,bb0.y,bb0.z,bb0.w, bb1.x,bb1.y,bb1.z,bb1.w};

    float* Ap = Ao + (size_t)p*TT*TT;
    #pragma unroll
    for (int i=0;i<8;i++){
        #pragma unroll
        for (int j=0;j<8;j++) v[i][j] += bv[j];
        float m = v[i][0];
        #pragma unroll
        for (int j=1;j<8;j++) m = fmaxf(m, v[i][j]);
        #pragma unroll
        for (int o=8;o>=1;o>>=1) m = fmaxf(m, __shfl_xor_sync(0xffffffffu, m, o));
        float s = 0.f;
        #pragma unroll
        for (int j=0;j<8;j++){ v[i][j] = expf(v[i][j] - m); s += v[i][j]; }
        #pragma unroll
        for (int o=8;o>=1;o>>=1) s += __shfl_xor_sync(0xffffffffu, s, o);
        float r = 1.f / s;
        int row = row_of(i, ty);
        *(float4*)(Ap + (size_t)row*TT + tx*4) =
            make_float4(v[i][0]*r, v[i][1]*r, v[i][2]*r, v[i][3]*r);
        *(float4*)(Ap + (size_t)row*TT + 64 + tx*4) =
            make_float4(v[i][4]*r, v[i][5]*r, v[i][6]*r, v[i][7]*r);
    }
}

// ================= K5: fused V = X_p @ Wv^T (tile in smem), then O = A @ V ===============
__global__ void __launch_bounds__(256, 2) kernel_VO(const float* __restrict__ node,
                                                    const float* __restrict__ neigh,
                                                    const float* __restrict__ Wv,
                                                    const float* Ain,
                                                    float* __restrict__ Out){
    extern __shared__ float sm[];
    float (*Vs)[128] = (float (*)[128])sm;                       // 128x128 = 64KB
    float (*As)[128] = (float (*)[128])(sm + 128*128);           // 16x128
    float (*Bs)[128] = (float (*)[128])(sm + 128*128 + 16*128);  // 16x128

    int tid = threadIdx.x, tx = tid & 15, ty = tid >> 4;
    int p = blockIdx.x;
    int n0 = blockIdx.y * 128;       // H column chunk
    const float* X  = pair_base(p, node, neigh);
    const float* Ap = ((Ain != nullptr) ? Ain : (const float*)g_Afb) + (size_t)p*TT*TT;

    ull acc[8][4];
    #pragma unroll
    for (int i=0;i<8;i++){ acc[i][0]=acc[i][1]=acc[i][2]=acc[i][3]=0ULL; }

    // ---- GEMM1: Vtile[s, c] = sum_k X[s,k] * Wv[n0+c, k] ----
    for (int kt = 0; kt < HH; kt += 16){
        stage_T(As, X + kt, HH, tid);                       // As[k][s]
        stage_T(Bs, Wv + (size_t)n0*HH + kt, HH, tid);      // Bs[k][c] = Wv[n0+c, kt+k]
        __syncthreads();
        mm16(acc, As, Bs, tx, ty);
        __syncthreads();
    }
    #pragma unroll
    for (int i=0;i<8;i++){
        int row = row_of(i, ty);
        float2 p0=upk(acc[i][0]), p1=upk(acc[i][1]), p2=upk(acc[i][2]), p3=upk(acc[i][3]);
        *(float4*)(&Vs[row][tx*4])      = make_float4(p0.x,p0.y,p1.x,p1.y);
        *(float4*)(&Vs[row][64+tx*4])   = make_float4(p2.x,p2.y,p3.x,p3.y);
        acc[i][0]=acc[i][1]=acc[i][2]=acc[i][3]=0ULL;
    }
    __syncthreads();

    // ---- GEMM2: O[t, c] = sum_s A[t,s] * Vs[s][c]  (K = 128) ----
    for (int kt = 0; kt < TT; kt += 16){
        stage_T(As, Ap + kt, TT, tid);                      // As[k][t] = A[t, kt+k]
        __syncthreads();
        mm16(acc, As, Vs + kt, tx, ty);                     // Bs := Vs rows kt..kt+15
        __syncthreads();
    }
    float* Ob = Out + (size_t)p*TT*HH + n0;
    #pragma unroll
    for (int i=0;i<8;i++){
        int row = row_of(i, ty);
        float2 p0=upk(acc[i][0]), p1=upk(acc[i][1]), p2=upk(acc[i][2]), p3=upk(acc[i][3]);
        *(float4*)(Ob + (size_t)row*HH + tx*4)      = make_float4(p0.x,p0.y,p1.x,p1.y);
        *(float4*)(Ob + (size_t)row*HH + 64 + tx*4) = make_float4(p2.x,p2.y,p3.x,p3.y);
    }
}

// =========================================================================================
extern "C" void kernel_launch(void* const* d_in, const int* in_sizes, int n_in,
                              void* d_out, int out_size){
    const float* node  = (const float*)d_in[0];
    const float* neigh = (const float*)d_in[1];
    // metadata order: node, neigh, neighbors_number(scalar), Wq, Wk, Wv, Wb, b
    // tolerate a harness that drops the scalar input
    int w = (n_in >= 8) ? 2 : 1;
    const float* Wq = (const float*)d_in[w+1];
    const float* Wk = (const float*)d_in[w+2];
    const float* Wv = (const float*)d_in[w+3];
    const float* Wb = (const float*)d_in[w+4];
    const float* bv = (const float*)d_in[w+5];

    float* out = (float*)d_out;
    const long long O_ELEMS = (long long)NPAIRS*TT*HH;   // 35,651,584
    const long long A_ELEMS = (long long)NPAIRS*TT*TT;   // 17,825,792
    // outputs first, then A (reference returns (outputs, A)); if the harness only
    // checks outputs, keep A in the device fallback buffer.
    float* Aout = ((long long)out_size >= O_ELEMS + A_ELEMS) ? (out + O_ELEMS) : nullptr;

    const int VO_SMEM = (128*128 + 2*16*128) * (int)sizeof(float);  // 81920 B
    cudaFuncSetAttribute(kernel_VO, cudaFuncAttributeMaxDynamicSharedMemorySize, VO_SMEM);

    dim3 thr(256);
    sgemm_flat<0><<<dim3(64,2), thr>>>(node, Wq);        // g_q  = node @ Wq^T
    sgemm_flat<1><<<dim3(64,2), thr>>>(nullptr, Wb);     // g_t2 = g_q @ Wb
    sgemm_flat<2><<<dim3(64,2), thr>>>(nullptr, Wk);     // g_P  = g_t2 @ Wk
    kernel_S <<<dim3(NPAIRS,1), thr>>>(node, neigh, bv, Aout);
    kernel_VO<<<dim3(NPAIRS,2), thr, VO_SMEM>>>(node, neigh, Wv, Aout, out);
}

// round 8
// speedup vs baseline: 1.0856x; 1.0812x over previous
#include <cuda_runtime.h>

typedef unsigned long long ull;

#define BB 64
#define NN 16
#define TT 128
#define HH 256
#define NP1 17
#define NPAIRS (BB*NP1)   // 1088
#define LDT 132           // padded smem row stride in floats (528B, 16B-aligned)

// ---------------- scratch (static device globals; no runtime allocation) ----------------
__device__ float g_q  [BB*TT*HH];     // node @ Wq^T
__device__ float g_t2 [BB*TT*HH];     // q @ Wb
__device__ float g_P  [BB*TT*HH];     // (q @ Wb) @ Wk
__device__ float g_Afb[(size_t)NPAIRS*TT*TT]; // fallback A buffer if A is not part of d_out

// ---------------- f32x2 helpers (Blackwell packed fp32, 2x FFMA throughput) -------------
__device__ __forceinline__ void fma2(ull& d, ull a, ull b){
    asm("fma.rn.f32x2 %0, %1, %2, %0;" : "+l"(d) : "l"(a), "l"(b));
}
__device__ __forceinline__ ull pk2(float x, float y){
    ull r; asm("mov.b64 %0, {%1, %2};" : "=l"(r) : "f"(x), "f"(y)); return r;
}
__device__ __forceinline__ float2 upk(ull v){
    float2 f; asm("mov.b64 {%0, %1}, %2;" : "=f"(f.x), "=f"(f.y) : "l"(v)); return f;
}

// ---------------- split staging: LDG into regs (prefetch) / STS after compute ----------
struct F8 { float4 a, b; };

// transpose path: smem[k][i] = src[i*ld + k]
__device__ __forceinline__ F8 ldg_T(const float* __restrict__ src, int ld, int tid){
    int c4 = (tid & 3) * 4;   // k offset (float4 group)
    int r  = tid >> 2;        // 0..63
    F8 f;
    f.a = *(const float4*)(src + (size_t)r*ld + c4);
    f.b = *(const float4*)(src + (size_t)(r+64)*ld + c4);
    return f;
}
__device__ __forceinline__ void sts_T(float (*dst)[LDT], F8 f, int tid){
    int c4 = (tid & 3) * 4;
    int r  = tid >> 2;
    dst[c4+0][r]    = f.a.x; dst[c4+1][r]    = f.a.y;
    dst[c4+2][r]    = f.a.z; dst[c4+3][r]    = f.a.w;
    dst[c4+0][r+64] = f.b.x; dst[c4+1][r+64] = f.b.y;
    dst[c4+2][r+64] = f.b.z; dst[c4+3][r+64] = f.b.w;
}
// direct path: smem[k][n] = src[k*ld + n]
__device__ __forceinline__ F8 ldg_D(const float* __restrict__ src, int ld, int tid){
    int n4 = (tid & 15) * 4;
    int k  = tid >> 4;        // 0..15
    F8 f;
    f.a = *(const float4*)(src + (size_t)k*ld + n4);
    f.b = *(const float4*)(src + (size_t)k*ld + n4 + 64);
    return f;
}
__device__ __forceinline__ void sts_D(float (*dst)[LDT], F8 f, int tid){
    int n4 = (tid & 15) * 4;
    int k  = tid >> 4;
    *(float4*)(&dst[k][n4])      = f.a;
    *(float4*)(&dst[k][n4 + 64]) = f.b;
}

// ---------------- 128x128 tile micro-kernel, one BK=16 slab ----------------
__device__ __forceinline__ void mm16(ull acc[8][4], const float (*As)[LDT],
                                     const float (*Bs)[LDT], int tx, int ty){
    #pragma unroll
    for (int k = 0; k < 16; ++k){
        float4 a0 = *(const float4*)(&As[k][ty*4]);
        float4 a1 = *(const float4*)(&As[k][64+ty*4]);
        float4 b0 = *(const float4*)(&Bs[k][tx*4]);
        float4 b1 = *(const float4*)(&Bs[k][64+tx*4]);
        ull bb0 = pk2(b0.x,b0.y), bb1 = pk2(b0.z,b0.w);
        ull bb2 = pk2(b1.x,b1.y), bb3 = pk2(b1.z,b1.w);
        float av[8] = {a0.x,a0.y,a0.z,a0.w,a1.x,a1.y,a1.z,a1.w};
        #pragma unroll
        for (int i = 0; i < 8; ++i){
            ull ad = pk2(av[i], av[i]);
            fma2(acc[i][0], ad, bb0);
            fma2(acc[i][1], ad, bb1);
            fma2(acc[i][2], ad, bb2);
            fma2(acc[i][3], ad, bb3);
        }
    }
}

__device__ __forceinline__ int row_of(int i, int ty){
    return (i < 4) ? (ty*4 + i) : (64 + ty*4 + (i-4));
}

__device__ __forceinline__ const float* pair_base(int p, const float* node, const float* neigh){
    int b = p / NP1, n = p % NP1;
    return (n == 0) ? node  + (size_t)b*TT*HH
                    : neigh + (size_t)(b*NN + (n-1))*TT*HH;
}

// ================= K1..K3: flat [8192,256] x [256,256] GEMM chain ========================
template<int STEP>
__global__ void __launch_bounds__(256, 2) sgemm_flat(const float* __restrict__ Ain,
                                                     const float* __restrict__ W){
    __shared__ __align__(16) float As[2][16][LDT], Bs[2][16][LDT];
    int tid = threadIdx.x, tx = tid & 15, ty = tid >> 4;
    const float* A = (STEP == 0) ? Ain : (STEP == 1 ? g_q : g_t2);
    float*       C = (STEP == 0) ? g_q : (STEP == 1 ? g_t2 : g_P);
    const float* Ab = A + (size_t)blockIdx.x * 128 * HH;
    int n0 = blockIdx.y * 128;
    const float* Bb = (STEP == 0) ? W + (size_t)n0*HH : W + n0;

    ull acc[8][4];
    #pragma unroll
    for (int i=0;i<8;i++){ acc[i][0]=acc[i][1]=acc[i][2]=acc[i][3]=0ULL; }

    F8 ra = ldg_T(Ab, HH, tid);
    F8 rb = (STEP == 0) ? ldg_T(Bb, HH, tid) : ldg_D(Bb, HH, tid);
    sts_T(As[0], ra, tid);
    if (STEP == 0) sts_T(Bs[0], rb, tid); else sts_D(Bs[0], rb, tid);
    __syncthreads();

    #pragma unroll 2
    for (int s = 0; s < 16; ++s){
        if (s < 15){
            ra = ldg_T(Ab + (s+1)*16, HH, tid);
            rb = (STEP == 0) ? ldg_T(Bb + (s+1)*16, HH, tid)
                             : ldg_D(Bb + (size_t)(s+1)*16*HH, HH, tid);
        }
        mm16(acc, As[s&1], Bs[s&1], tx, ty);
        if (s < 15){
            sts_T(As[(s+1)&1], ra, tid);
            if (STEP == 0) sts_T(Bs[(s+1)&1], rb, tid); else sts_D(Bs[(s+1)&1], rb, tid);
        }
        __syncthreads();
    }

    float* Cb = C + (size_t)blockIdx.x*128*HH + n0;
    #pragma unroll
    for (int i=0;i<8;i++){
        int row = row_of(i, ty);
        float2 p0=upk(acc[i][0]), p1=upk(acc[i][1]), p2=upk(acc[i][2]), p3=upk(acc[i][3]);
        *(float4*)(Cb + (size_t)row*HH + tx*4)      = make_float4(p0.x,p0.y,p1.x,p1.y);
        *(float4*)(Cb + (size_t)row*HH + 64 + tx*4) = make_float4(p2.x,p2.y,p3.x,p3.y);
    }
}

// ================= K4: S = P_b @ X_p^T  (+bias) -> softmax -> A ==========================
__global__ void __launch_bounds__(256, 2) kernel_S(const float* __restrict__ node,
                                                   const float* __restrict__ neigh,
                                                   const float* __restrict__ bias,
                                                   float* Aout){
    __shared__ __align__(16) float As[2][16][LDT], Bs[2][16][LDT];
    int tid = threadIdx.x, tx = tid & 15, ty = tid >> 4;
    int p = blockIdx.x, b = p / NP1;
    const float* Pb = g_P + (size_t)b*TT*HH;
    const float* X  = pair_base(p, node, neigh);
    float* Ao = (Aout != nullptr) ? Aout : g_Afb;

    ull acc[8][4];
    #pragma unroll
    for (int i=0;i<8;i++){ acc[i][0]=acc[i][1]=acc[i][2]=acc[i][3]=0ULL; }

    F8 ra = ldg_T(Pb, HH, tid);
    F8 rb = ldg_T(X,  HH, tid);
    sts_T(As[0], ra, tid);
    sts_T(Bs[0], rb, tid);
    __syncthreads();

    #pragma unroll 2
    for (int s = 0; s < 16; ++s){
        if (s < 15){
            ra = ldg_T(Pb + (s+1)*16, HH, tid);
            rb = ldg_T(X  + (s+1)*16, HH, tid);
        }
        mm16(acc, As[s&1], Bs[s&1], tx, ty);
        if (s < 15){
            sts_T(As[(s+1)&1], ra, tid);
            sts_T(Bs[(s+1)&1], rb, tid);
        }
        __syncthreads();
    }

    // unpack S, add bias (broadcast over s), softmax over s (cols of the tile)
    float v[8][8];
    #pragma unroll
    for (int i=0;i<8;i++){
        float2 p0=upk(acc[i][0]), p1=upk(acc[i][1]), p2=upk(acc[i][2]), p3=upk(acc[i][3]);
        v[i][0]=p0.x; v[i][1]=p0.y; v[i][2]=p1.x; v[i][3]=p1.y;
        v[i][4]=p2.x; v[i][5]=p2.y; v[i][6]=p3.x; v[i][7]=p3.y;
    }
    float4 bb0 = *(const float4*)(bias + tx*4);
    float4 bb1 = *(const float4*)(bias + 64 + tx*4);
    float bv[8] = {bb0.x,bb0.y,bb0.z,bb0.w, bb1.x,bb1.y,bb1.z,bb1.w};

    float* Ap = Ao + (size_t)p*TT*TT;
    #pragma unroll
    for (int i=0;i<8;i++){
        #pragma unroll
        for (int j=0;j<8;j++) v[i][j] += bv[j];
        float m = v[i][0];
        #pragma unroll
        for (int j=1;j<8;j++) m = fmaxf(m, v[i][j]);
        #pragma unroll
        for (int o=8;o>=1;o>>=1) m = fmaxf(m, __shfl_xor_sync(0xffffffffu, m, o));
        float s = 0.f;
        #pragma unroll
        for (int j=0;j<8;j++){ v[i][j] = __expf(v[i][j] - m); s += v[i][j]; }
        #pragma unroll
        for (int o=8;o>=1;o>>=1) s += __shfl_xor_sync(0xffffffffu, s, o);
        float r = 1.f / s;
        int row = row_of(i, ty);
        *(float4*)(Ap + (size_t)row*TT + tx*4) =
            make_float4(v[i][0]*r, v[i][1]*r, v[i][2]*r, v[i][3]*r);
        *(float4*)(Ap + (size_t)row*TT + 64 + tx*4) =
            make_float4(v[i][4]*r, v[i][5]*r, v[i][6]*r, v[i][7]*r);
    }
}

// ================= K5: fused V = X_p @ Wv^T (tile in smem), then O = A @ V ===============
__global__ void __launch_bounds__(256, 2) kernel_VO(const float* __restrict__ node,
                                                    const float* __restrict__ neigh,
                                                    const float* __restrict__ Wv,
                                                    const float* Ain,
                                                    float* __restrict__ Out){
    extern __shared__ float sm[];
    float (*Vs)[LDT]      = (float (*)[LDT])sm;                             // 128xLDT
    float (*As2)[16][LDT] = (float (*)[16][LDT])(sm + 128*LDT);             // 2 bufs
    float (*Bs2)[16][LDT] = (float (*)[16][LDT])(sm + 128*LDT + 2*16*LDT);  // 2 bufs

    int tid = threadIdx.x, tx = tid & 15, ty = tid >> 4;
    int p = blockIdx.x;
    int n0 = blockIdx.y * 128;       // H column chunk
    const float* X  = pair_base(p, node, neigh);
    const float* Wb = Wv + (size_t)n0*HH;
    const float* Ap = ((Ain != nullptr) ? Ain : (const float*)g_Afb) + (size_t)p*TT*TT;

    ull acc[8][4];
    #pragma unroll
    for (int i=0;i<8;i++){ acc[i][0]=acc[i][1]=acc[i][2]=acc[i][3]=0ULL; }

    // ---- GEMM1: Vtile[s, c] = sum_k X[s,k] * Wv[n0+c, k] ----
    {
        F8 ra = ldg_T(X,  HH, tid);
        F8 rb = ldg_T(Wb, HH, tid);
        sts_T(As2[0], ra, tid);
        sts_T(Bs2[0], rb, tid);
        __syncthreads();
        #pragma unroll 2
        for (int s = 0; s < 16; ++s){
            if (s < 15){
                ra = ldg_T(X  + (s+1)*16, HH, tid);
                rb = ldg_T(Wb + (s+1)*16, HH, tid);
            }
            mm16(acc, As2[s&1], Bs2[s&1], tx, ty);
            if (s < 15){
                sts_T(As2[(s+1)&1], ra, tid);
                sts_T(Bs2[(s+1)&1], rb, tid);
            }
            __syncthreads();
        }
    }
    // write Vtile to smem, reset acc, prefetch GEMM2 slab 0 (As2[0] is free after last sync)
    #pragma unroll
    for (int i=0;i<8;i++){
        int row = row_of(i, ty);
        float2 p0=upk(acc[i][0]), p1=upk(acc[i][1]), p2=upk(acc[i][2]), p3=upk(acc[i][3]);
        *(float4*)(&Vs[row][tx*4])    = make_float4(p0.x,p0.y,p1.x,p1.y);
        *(float4*)(&Vs[row][64+tx*4]) = make_float4(p2.x,p2.y,p3.x,p3.y);
        acc[i][0]=acc[i][1]=acc[i][2]=acc[i][3]=0ULL;
    }
    {
        F8 ra = ldg_T(Ap, TT, tid);
        sts_T(As2[0], ra, tid);
    }
    __syncthreads();

    // ---- GEMM2: O[t, c] = sum_s A[t,s] * Vs[s][c]  (K = 128, B resident in smem) ----
    #pragma unroll 2
    for (int s = 0; s < 8; ++s){
        F8 ra;
        if (s < 7) ra = ldg_T(Ap + (s+1)*16, TT, tid);
        mm16(acc, As2[s&1], Vs + s*16, tx, ty);
        if (s < 7) sts_T(As2[(s+1)&1], ra, tid);
        __syncthreads();
    }

    float* Ob = Out + (size_t)p*TT*HH + n0;
    #pragma unroll
    for (int i=0;i<8;i++){
        int row = row_of(i, ty);
        float2 p0=upk(acc[i][0]), p1=upk(acc[i][1]), p2=upk(acc[i][2]), p3=upk(acc[i][3]);
        *(float4*)(Ob + (size_t)row*HH + tx*4)      = make_float4(p0.x,p0.y,p1.x,p1.y);
        *(float4*)(Ob + (size_t)row*HH + 64 + tx*4) = make_float4(p2.x,p2.y,p3.x,p3.y);
    }
}

// =========================================================================================
extern "C" void kernel_launch(void* const* d_in, const int* in_sizes, int n_in,
                              void* d_out, int out_size){
    const float* node  = (const float*)d_in[0];
    const float* neigh = (const float*)d_in[1];
    // metadata order: node, neigh, neighbors_number(scalar), Wq, Wk, Wv, Wb, b
    int w = (n_in >= 8) ? 2 : 1;
    const float* Wq = (const float*)d_in[w+1];
    const float* Wk = (const float*)d_in[w+2];
    const float* Wv = (const float*)d_in[w+3];
    const float* Wb = (const float*)d_in[w+4];
    const float* bv = (const float*)d_in[w+5];

    float* out = (float*)d_out;
    const long long O_ELEMS = (long long)NPAIRS*TT*HH;   // 35,651,584
    const long long A_ELEMS = (long long)NPAIRS*TT*TT;   // 17,825,792
    float* Aout = ((long long)out_size >= O_ELEMS + A_ELEMS) ? (out + O_ELEMS) : nullptr;

    const int VO_SMEM = (128*LDT + 4*16*LDT) * (int)sizeof(float);  // 101,376 B
    cudaFuncSetAttribute(kernel_VO, cudaFuncAttributeMaxDynamicSharedMemorySize, VO_SMEM);

    dim3 thr(256);
    sgemm_flat<0><<<dim3(64,2), thr>>>(node, Wq);        // g_q  = node @ Wq^T
    sgemm_flat<1><<<dim3(64,2), thr>>>(nullptr, Wb);     // g_t2 = g_q @ Wb
    sgemm_flat<2><<<dim3(64,2), thr>>>(nullptr, Wk);     // g_P  = g_t2 @ Wk
    kernel_S <<<dim3(NPAIRS,1), thr>>>(node, neigh, bv, Aout);
    kernel_VO<<<dim3(NPAIRS,2), thr, VO_SMEM>>>(node, neigh, Wv, Aout, out);
}